// round 4
// baseline (speedup 1.0000x reference)
#include <cuda_runtime.h>
#include <cuda_bf16.h>
#include <math.h>
#include <stdint.h>

// Problem shape (fixed): N=8, C=128, H=W=32 -> HW=1024.
#define NB   8
#define CC   128
#define HW   1024
#define BM   128
#define BN   128
#define BK   64

#define NPIX (NB * HW)      // 8192
#define NTILES (8 * 8 * 8)  // 512 CTAs in tile grid

// ---------------------------------------------------------------------------
// Device scratch (allocation-free rule: __device__ globals)
// ---------------------------------------------------------------------------
__device__ __nv_bfloat16 g_Rbf[NB * CC * HW];
__device__ __nv_bfloat16 g_Ibf[NB * CC * HW];
__device__ float g_rnorm[NPIX];
__device__ float g_inorm[NPIX];
__device__ float g_rowL [NPIX];
__device__ float g_rowLM[NPIX];
__device__ float g_colL [NPIX];
__device__ float g_colLM[NPIX];
__device__ unsigned int g_ctr;

// ---------------------------------------------------------------------------
// PTX helpers
// ---------------------------------------------------------------------------
__device__ __forceinline__ uint32_t smem_u32(const void* p) {
    return (uint32_t)__cvta_generic_to_shared(p);
}

__device__ __forceinline__ void ldsm_x4_t(uint32_t& r0, uint32_t& r1,
                                          uint32_t& r2, uint32_t& r3, uint32_t addr) {
    asm volatile("ldmatrix.sync.aligned.m8n8.x4.trans.shared.b16 {%0,%1,%2,%3}, [%4];"
                 : "=r"(r0), "=r"(r1), "=r"(r2), "=r"(r3) : "r"(addr));
}

__device__ __forceinline__ void ldsm_x2_t(uint32_t& r0, uint32_t& r1, uint32_t addr) {
    asm volatile("ldmatrix.sync.aligned.m8n8.x2.trans.shared.b16 {%0,%1}, [%2];"
                 : "=r"(r0), "=r"(r1) : "r"(addr));
}

__device__ __forceinline__ void mma_bf16(float& d0, float& d1, float& d2, float& d3,
                                         uint32_t a0, uint32_t a1, uint32_t a2, uint32_t a3,
                                         uint32_t b0, uint32_t b1) {
    asm volatile("mma.sync.aligned.m16n8k16.row.col.f32.bf16.bf16.f32 "
                 "{%0,%1,%2,%3}, {%4,%5,%6,%7}, {%8,%9}, {%0,%1,%2,%3};"
                 : "+f"(d0), "+f"(d1), "+f"(d2), "+f"(d3)
                 : "r"(a0), "r"(a1), "r"(a2), "r"(a3), "r"(b0), "r"(b1));
}

// ---------------------------------------------------------------------------
// prep: norms (atomic-free) + fp32->bf16 convert + zero all accumulators.
// 128 blocks x 256 threads. Block b handles pixels [b*64, b*64+64); thread
// quarter q = tid>>6 handles channels [q*32, q*32+32) for pixel b*64+(tid&63).
// ---------------------------------------------------------------------------
__global__ __launch_bounds__(256)
void prep_kernel(const float* __restrict__ R, const float* __restrict__ I)
{
    __shared__ float s_r[4][64];
    __shared__ float s_i[4][64];

    const int tid = threadIdx.x;
    const int px  = (blockIdx.x << 6) + (tid & 63);   // global pixel 0..8191
    const int q   = tid >> 6;                          // channel quarter 0..3
    const int n   = px >> 10;
    const int p   = px & (HW - 1);

    const float* a  = R + n * CC * HW + (q * 32) * HW + p;
    const float* bb = I + n * CC * HW + (q * 32) * HW + p;
    __nv_bfloat16* oa = g_Rbf + n * CC * HW + (q * 32) * HW + p;
    __nv_bfloat16* ob = g_Ibf + n * CC * HW + (q * 32) * HW + p;

    float sa = 0.f, sb = 0.f;
    #pragma unroll 8
    for (int c = 0; c < 32; c++) {
        float va = a[c * HW];
        float vb = bb[c * HW];
        oa[c * HW] = __float2bfloat16(va);
        ob[c * HW] = __float2bfloat16(vb);
        sa = fmaf(va, va, sa);
        sb = fmaf(vb, vb, sb);
    }
    s_r[q][tid & 63] = sa;
    s_i[q][tid & 63] = sb;
    __syncthreads();

    if (tid < 64) {
        g_rnorm[px] = s_r[0][tid] + s_r[1][tid] + s_r[2][tid] + s_r[3][tid];
    } else if (tid < 128) {
        int t = tid - 64;
        int px2 = (blockIdx.x << 6) + t;
        g_inorm[px2] = s_i[0][t] + s_i[1][t] + s_i[2][t] + s_i[3][t];
    }

    // Zero accumulators: 128*256 = 32768 threads = 4 arrays x 8192.
    int idx = blockIdx.x * 256 + tid;
    int arr = idx >> 13;
    int pos = idx & (NPIX - 1);
    if      (arr == 0) g_rowL [pos] = 0.f;
    else if (arr == 1) g_rowLM[pos] = 0.f;
    else if (arr == 2) g_colL [pos] = 0.f;
    else               g_colLM[pos] = 0.f;
    if (idx == 0) g_ctr = 0u;
}

// ---------------------------------------------------------------------------
// fused bf16 tensor-core tile kernel + last-CTA finalize.
// ---------------------------------------------------------------------------
__global__ __launch_bounds__(256, 2)
void tile_kernel(const int* __restrict__ RM, const int* __restrict__ IM,
                 float* __restrict__ out)
{
    __shared__ __nv_bfloat16 As[BK][BM + 8];
    __shared__ __nv_bfloat16 Bs[BK][BN + 8];

    const int n  = blockIdx.z;
    const int p0 = blockIdx.y * BM;
    const int q0 = blockIdx.x * BN;
    const int tid  = threadIdx.x;
    const int wid  = tid >> 5;
    const int lane = tid & 31;
    const int warp_m = wid >> 2;   // 0..1
    const int warp_n = wid & 3;    // 0..3

    const __nv_bfloat16* Rb = g_Rbf + n * CC * HW;
    const __nv_bfloat16* Ib = g_Ibf + n * CC * HW;

    float acc[4][4][4];
    #pragma unroll
    for (int mi = 0; mi < 4; mi++)
        #pragma unroll
        for (int ni = 0; ni < 4; ni++)
            #pragma unroll
            for (int r = 0; r < 4; r++)
                acc[mi][ni][r] = 0.f;

    const int sub   = lane >> 3;
    const int lrow  = lane & 7;
    const int a_kad = lrow + ((sub >> 1) ? 8 : 0);
    const int a_mad = warp_m * 64 + ((sub & 1) ? 8 : 0);
    const int b_kad = lrow + (((lane >> 3) & 1) ? 8 : 0);

    for (int kk = 0; kk < CC; kk += BK) {
        #pragma unroll
        for (int l = 0; l < 4; l++) {
            int f   = tid + l * 256;   // uint4 index 0..1023
            int row = f >> 4;          // 16 uint4 per 128-elem row
            int c8  = (f & 15) * 8;
            uint4 va = *reinterpret_cast<const uint4*>(Rb + (kk + row) * HW + p0 + c8);
            *reinterpret_cast<uint4*>(&As[row][c8]) = va;
            uint4 vb = *reinterpret_cast<const uint4*>(Ib + (kk + row) * HW + q0 + c8);
            *reinterpret_cast<uint4*>(&Bs[row][c8]) = vb;
        }
        __syncthreads();

        #pragma unroll
        for (int ks = 0; ks < BK / 16; ks++) {
            const int k0 = ks * 16;
            uint32_t afr[4][4];
            #pragma unroll
            for (int mi = 0; mi < 4; mi++) {
                uint32_t addr = smem_u32(&As[k0 + a_kad][a_mad + mi * 16]);
                ldsm_x4_t(afr[mi][0], afr[mi][1], afr[mi][2], afr[mi][3], addr);
            }
            uint32_t bfr[4][2];
            #pragma unroll
            for (int ni = 0; ni < 4; ni++) {
                uint32_t addr = smem_u32(&Bs[k0 + b_kad][warp_n * 32 + ni * 8]);
                ldsm_x2_t(bfr[ni][0], bfr[ni][1], addr);
            }
            #pragma unroll
            for (int mi = 0; mi < 4; mi++)
                #pragma unroll
                for (int ni = 0; ni < 4; ni++)
                    mma_bf16(acc[mi][ni][0], acc[mi][ni][1], acc[mi][ni][2], acc[mi][ni][3],
                             afr[mi][0], afr[mi][1], afr[mi][2], afr[mi][3],
                             bfr[ni][0], bfr[ni][1]);
        }
        __syncthreads();
    }

    // --------------------------- fused epilogue ---------------------------
    const int g  = lane >> 2;
    const int tg = lane & 3;
    const int base = n * HW;

    float rn2[4][2]; int rm2[4][2];
    #pragma unroll
    for (int mi = 0; mi < 4; mi++) {
        int r = p0 + warp_m * 64 + mi * 16 + g;
        rn2[mi][0] = g_rnorm[base + r];     rm2[mi][0] = RM[base + r];
        rn2[mi][1] = g_rnorm[base + r + 8]; rm2[mi][1] = RM[base + r + 8];
    }
    float in2[4][2]; int im2[4][2];
    #pragma unroll
    for (int ni = 0; ni < 4; ni++) {
        int c = q0 + warp_n * 32 + ni * 8 + tg * 2;
        in2[ni][0] = g_inorm[base + c];     im2[ni][0] = IM[base + c];
        in2[ni][1] = g_inorm[base + c + 1]; im2[ni][1] = IM[base + c + 1];
    }

    // Convert acc -> dist in place; track thread-local min.
    float mind = 1e30f;
    #pragma unroll
    for (int mi = 0; mi < 4; mi++)
        #pragma unroll
        for (int ni = 0; ni < 4; ni++)
            #pragma unroll
            for (int r = 0; r < 4; r++) {
                float d = rn2[mi][r >> 1] + in2[ni][r & 1] - 2.0f * acc[mi][ni][r];
                acc[mi][ni][r] = d;
                mind = fminf(mind, d);
            }

    float rowS[4][2], rowM[4][2], colS[4][2], colM[4][2];
    #pragma unroll
    for (int i = 0; i < 4; i++)
        #pragma unroll
        for (int j = 0; j < 2; j++) {
            rowS[i][j] = 0.f; rowM[i][j] = 0.f;
            colS[i][j] = 0.f; colM[i][j] = 0.f;
        }

    if (mind > 18.0f) {
        // Exact fast path: dist > 18 => expf(-dist) < 2^-25 =>
        // expf(e1/10) rounds to exactly 1.0f in fp32 (same as reference).
        #pragma unroll
        for (int mi = 0; mi < 4; mi++)
            #pragma unroll
            for (int ni = 0; ni < 4; ni++)
                #pragma unroll
                for (int r = 0; r < 4; r++) {
                    int ri = r >> 1, ci = r & 1;
                    rowS[mi][ri] += 1.0f;
                    colS[ni][ci] += 1.0f;
                    if (rm2[mi][ri] == im2[ni][ci]) {
                        rowM[mi][ri] += 1.0f;
                        colM[ni][ci] += 1.0f;
                    }
                }
    } else {
        #pragma unroll
        for (int mi = 0; mi < 4; mi++)
            #pragma unroll
            for (int ni = 0; ni < 4; ni++)
                #pragma unroll
                for (int r = 0; r < 4; r++) {
                    int ri = r >> 1, ci = r & 1;
                    float d = acc[mi][ni][r];
                    float logit = (d > 18.0f) ? 1.0f
                                              : __expf(__expf(-d) * 0.1f);
                    rowS[mi][ri] += logit;
                    colS[ni][ci] += logit;
                    if (rm2[mi][ri] == im2[ni][ci]) {
                        rowM[mi][ri] += logit;
                        colM[ni][ci] += logit;
                    }
                }
    }

    // Row reduce across tg: xor 1, 2.
    #pragma unroll
    for (int mi = 0; mi < 4; mi++)
        #pragma unroll
        for (int ri = 0; ri < 2; ri++) {
            float v = rowS[mi][ri], m = rowM[mi][ri];
            v += __shfl_xor_sync(0xffffffffu, v, 1);
            v += __shfl_xor_sync(0xffffffffu, v, 2);
            m += __shfl_xor_sync(0xffffffffu, m, 1);
            m += __shfl_xor_sync(0xffffffffu, m, 2);
            if (tg == 0) {
                int r = p0 + warp_m * 64 + mi * 16 + g + ri * 8;
                atomicAdd(&g_rowL [base + r], v);
                atomicAdd(&g_rowLM[base + r], m);
            }
        }

    // Col reduce across g: xor 4, 8, 16.
    #pragma unroll
    for (int ni = 0; ni < 4; ni++)
        #pragma unroll
        for (int ci = 0; ci < 2; ci++) {
            float v = colS[ni][ci], m = colM[ni][ci];
            v += __shfl_xor_sync(0xffffffffu, v, 4);
            v += __shfl_xor_sync(0xffffffffu, v, 8);
            v += __shfl_xor_sync(0xffffffffu, v, 16);
            m += __shfl_xor_sync(0xffffffffu, m, 4);
            m += __shfl_xor_sync(0xffffffffu, m, 8);
            m += __shfl_xor_sync(0xffffffffu, m, 16);
            if (g == 0) {
                int c = q0 + warp_n * 32 + ni * 8 + tg * 2 + ci;
                atomicAdd(&g_colL [base + c], v);
                atomicAdd(&g_colLM[base + c], m);
            }
        }

    // ------------------- last-CTA finalize (reduce + div) -------------------
    __shared__ unsigned int s_rank;
    __threadfence();
    __syncthreads();
    if (tid == 0) s_rank = atomicAdd(&g_ctr, 1u);
    __syncthreads();
    if (s_rank != NTILES - 1) return;

    __shared__ float s_t[256];
    __shared__ float s_c[256];
    float tot = 0.f, cnt = 0.f;
    for (int j = tid; j < NPIX; j += 256) {
        {
            float l = g_rowL[j] + 1e-6f;
            float v = g_rowLM[j] / l;
            if (RM[j] > 0 && v != 0.0f) { tot -= __logf(v); cnt += 1.f; }
        }
        {
            float l = g_colL[j] + 1e-6f;
            float v = g_colLM[j] / l;
            if (IM[j] > 0 && v != 0.0f) { tot -= __logf(v); cnt += 1.f; }
        }
    }
    s_t[tid] = tot; s_c[tid] = cnt;
    __syncthreads();
    for (int s = 128; s > 0; s >>= 1) {
        if (tid < s) { s_t[tid] += s_t[tid + s]; s_c[tid] += s_c[tid + s]; }
        __syncthreads();
    }
    if (tid == 0) out[0] = s_t[0] / s_c[0];
}

// ---------------------------------------------------------------------------
extern "C" void kernel_launch(void* const* d_in, const int* in_sizes, int n_in,
                              void* d_out, int out_size)
{
    const float* R  = (const float*)d_in[0];   // rgb_map  (N,C,H,W) fp32
    const float* I  = (const float*)d_in[1];   // ir_map   (N,C,H,W) fp32
    const int*   RM = (const int*)  d_in[2];   // rgb_mask (N,H,W)   int32
    const int*   IM = (const int*)  d_in[3];   // ir_mask  (N,H,W)   int32
    float* out = (float*)d_out;

    prep_kernel<<<128, 256>>>(R, I);

    dim3 grid(HW / BN, HW / BM, NB);           // (8, 8, 8) = 512 CTAs
    tile_kernel<<<grid, 256>>>(RM, IM, out);
}

// round 5
// speedup vs baseline: 1.5681x; 1.5681x over previous
#include <cuda_runtime.h>
#include <cuda_bf16.h>
#include <math.h>
#include <stdint.h>

// Problem shape (fixed): N=8, C=128, H=W=32 -> HW=1024.
#define NB   8
#define CC   128
#define HW   1024
#define BM   128
#define BN   128
#define BK   64

#define NPIX (NB * HW)      // 8192

// ---------------------------------------------------------------------------
// Device scratch (allocation-free rule: __device__ globals)
// ---------------------------------------------------------------------------
__device__ __nv_bfloat16 g_Rbf[NB * CC * HW];
__device__ __nv_bfloat16 g_Ibf[NB * CC * HW];
__device__ float g_rnorm[NPIX];
__device__ float g_inorm[NPIX];
__device__ float g_rowL [NPIX];
__device__ float g_rowLM[NPIX];
__device__ float g_colL [NPIX];
__device__ float g_colLM[NPIX];

// ---------------------------------------------------------------------------
// PTX helpers
// ---------------------------------------------------------------------------
__device__ __forceinline__ uint32_t smem_u32(const void* p) {
    return (uint32_t)__cvta_generic_to_shared(p);
}

__device__ __forceinline__ void ldsm_x4_t(uint32_t& r0, uint32_t& r1,
                                          uint32_t& r2, uint32_t& r3, uint32_t addr) {
    asm volatile("ldmatrix.sync.aligned.m8n8.x4.trans.shared.b16 {%0,%1,%2,%3}, [%4];"
                 : "=r"(r0), "=r"(r1), "=r"(r2), "=r"(r3) : "r"(addr));
}

__device__ __forceinline__ void ldsm_x2_t(uint32_t& r0, uint32_t& r1, uint32_t addr) {
    asm volatile("ldmatrix.sync.aligned.m8n8.x2.trans.shared.b16 {%0,%1}, [%2];"
                 : "=r"(r0), "=r"(r1) : "r"(addr));
}

__device__ __forceinline__ void mma_bf16(float& d0, float& d1, float& d2, float& d3,
                                         uint32_t a0, uint32_t a1, uint32_t a2, uint32_t a3,
                                         uint32_t b0, uint32_t b1) {
    asm volatile("mma.sync.aligned.m16n8k16.row.col.f32.bf16.bf16.f32 "
                 "{%0,%1,%2,%3}, {%4,%5,%6,%7}, {%8,%9}, {%0,%1,%2,%3};"
                 : "+f"(d0), "+f"(d1), "+f"(d2), "+f"(d3)
                 : "r"(a0), "r"(a1), "r"(a2), "r"(a3), "r"(b0), "r"(b1));
}

// ---------------------------------------------------------------------------
// prep: norms (atomic-free) + fp32->bf16 convert + zero all accumulators.
// 128 blocks x 256 threads.
// ---------------------------------------------------------------------------
__global__ __launch_bounds__(256)
void prep_kernel(const float* __restrict__ R, const float* __restrict__ I)
{
    __shared__ float s_r[4][64];
    __shared__ float s_i[4][64];

    const int tid = threadIdx.x;
    const int px  = (blockIdx.x << 6) + (tid & 63);   // global pixel 0..8191
    const int q   = tid >> 6;                          // channel quarter 0..3
    const int n   = px >> 10;
    const int p   = px & (HW - 1);

    const float* a  = R + n * CC * HW + (q * 32) * HW + p;
    const float* bb = I + n * CC * HW + (q * 32) * HW + p;
    __nv_bfloat16* oa = g_Rbf + n * CC * HW + (q * 32) * HW + p;
    __nv_bfloat16* ob = g_Ibf + n * CC * HW + (q * 32) * HW + p;

    float sa = 0.f, sb = 0.f;
    #pragma unroll 8
    for (int c = 0; c < 32; c++) {
        float va = a[c * HW];
        float vb = bb[c * HW];
        oa[c * HW] = __float2bfloat16(va);
        ob[c * HW] = __float2bfloat16(vb);
        sa = fmaf(va, va, sa);
        sb = fmaf(vb, vb, sb);
    }
    s_r[q][tid & 63] = sa;
    s_i[q][tid & 63] = sb;
    __syncthreads();

    if (tid < 64) {
        g_rnorm[px] = s_r[0][tid] + s_r[1][tid] + s_r[2][tid] + s_r[3][tid];
    } else if (tid < 128) {
        int t = tid - 64;
        int px2 = (blockIdx.x << 6) + t;
        g_inorm[px2] = s_i[0][t] + s_i[1][t] + s_i[2][t] + s_i[3][t];
    }

    // Zero accumulators: 128*256 = 32768 threads = 4 arrays x 8192.
    int idx = blockIdx.x * 256 + tid;
    int arr = idx >> 13;
    int pos = idx & (NPIX - 1);
    if      (arr == 0) g_rowL [pos] = 0.f;
    else if (arr == 1) g_rowLM[pos] = 0.f;
    else if (arr == 2) g_colL [pos] = 0.f;
    else               g_colLM[pos] = 0.f;
}

// ---------------------------------------------------------------------------
// fused bf16 tensor-core tile kernel: 128x128 (p,q) tile per CTA.
// ---------------------------------------------------------------------------
__global__ __launch_bounds__(256, 2)
void tile_kernel(const int* __restrict__ RM, const int* __restrict__ IM)
{
    __shared__ __nv_bfloat16 As[BK][BM + 8];
    __shared__ __nv_bfloat16 Bs[BK][BN + 8];

    const int n  = blockIdx.z;
    const int p0 = blockIdx.y * BM;
    const int q0 = blockIdx.x * BN;
    const int tid  = threadIdx.x;
    const int wid  = tid >> 5;
    const int lane = tid & 31;
    const int warp_m = wid >> 2;   // 0..1
    const int warp_n = wid & 3;    // 0..3

    const __nv_bfloat16* Rb = g_Rbf + n * CC * HW;
    const __nv_bfloat16* Ib = g_Ibf + n * CC * HW;

    float acc[4][4][4];
    #pragma unroll
    for (int mi = 0; mi < 4; mi++)
        #pragma unroll
        for (int ni = 0; ni < 4; ni++)
            #pragma unroll
            for (int r = 0; r < 4; r++)
                acc[mi][ni][r] = 0.f;

    const int sub   = lane >> 3;
    const int lrow  = lane & 7;
    const int a_kad = lrow + ((sub >> 1) ? 8 : 0);
    const int a_mad = warp_m * 64 + ((sub & 1) ? 8 : 0);
    const int b_kad = lrow + (((lane >> 3) & 1) ? 8 : 0);

    for (int kk = 0; kk < CC; kk += BK) {
        #pragma unroll
        for (int l = 0; l < 4; l++) {
            int f   = tid + l * 256;   // uint4 index 0..1023
            int row = f >> 4;          // 16 uint4 per 128-elem row
            int c8  = (f & 15) * 8;
            uint4 va = *reinterpret_cast<const uint4*>(Rb + (kk + row) * HW + p0 + c8);
            *reinterpret_cast<uint4*>(&As[row][c8]) = va;
            uint4 vb = *reinterpret_cast<const uint4*>(Ib + (kk + row) * HW + q0 + c8);
            *reinterpret_cast<uint4*>(&Bs[row][c8]) = vb;
        }
        __syncthreads();

        #pragma unroll
        for (int ks = 0; ks < BK / 16; ks++) {
            const int k0 = ks * 16;
            uint32_t afr[4][4];
            #pragma unroll
            for (int mi = 0; mi < 4; mi++) {
                uint32_t addr = smem_u32(&As[k0 + a_kad][a_mad + mi * 16]);
                ldsm_x4_t(afr[mi][0], afr[mi][1], afr[mi][2], afr[mi][3], addr);
            }
            uint32_t bfr[4][2];
            #pragma unroll
            for (int ni = 0; ni < 4; ni++) {
                uint32_t addr = smem_u32(&Bs[k0 + b_kad][warp_n * 32 + ni * 8]);
                ldsm_x2_t(bfr[ni][0], bfr[ni][1], addr);
            }
            #pragma unroll
            for (int mi = 0; mi < 4; mi++)
                #pragma unroll
                for (int ni = 0; ni < 4; ni++)
                    mma_bf16(acc[mi][ni][0], acc[mi][ni][1], acc[mi][ni][2], acc[mi][ni][3],
                             afr[mi][0], afr[mi][1], afr[mi][2], afr[mi][3],
                             bfr[ni][0], bfr[ni][1]);
        }
        __syncthreads();
    }

    // --------------------------- fused epilogue ---------------------------
    const int g  = lane >> 2;
    const int tg = lane & 3;
    const int base = n * HW;

    float rn2[4][2]; int rm2[4][2];
    #pragma unroll
    for (int mi = 0; mi < 4; mi++) {
        int r = p0 + warp_m * 64 + mi * 16 + g;
        rn2[mi][0] = g_rnorm[base + r];     rm2[mi][0] = RM[base + r];
        rn2[mi][1] = g_rnorm[base + r + 8]; rm2[mi][1] = RM[base + r + 8];
    }
    float in2[4][2]; int im2[4][2];
    #pragma unroll
    for (int ni = 0; ni < 4; ni++) {
        int c = q0 + warp_n * 32 + ni * 8 + tg * 2;
        in2[ni][0] = g_inorm[base + c];     im2[ni][0] = IM[base + c];
        in2[ni][1] = g_inorm[base + c + 1]; im2[ni][1] = IM[base + c + 1];
    }

    // Convert acc -> dist in place; thread-local min, then WARP-UNIFORM vote.
    float mind = 1e30f;
    #pragma unroll
    for (int mi = 0; mi < 4; mi++)
        #pragma unroll
        for (int ni = 0; ni < 4; ni++)
            #pragma unroll
            for (int r = 0; r < 4; r++) {
                float d = rn2[mi][r >> 1] + in2[ni][r & 1] - 2.0f * acc[mi][ni][r];
                acc[mi][ni][r] = d;
                mind = fminf(mind, d);
            }
    const bool fast = __all_sync(0xffffffffu, mind > 18.0f);

    float rowS[4][2], rowM[4][2], colS[4][2], colM[4][2];
    #pragma unroll
    for (int i = 0; i < 4; i++)
        #pragma unroll
        for (int j = 0; j < 2; j++) {
            rowS[i][j] = 0.f; rowM[i][j] = 0.f;
            colS[i][j] = 0.f; colM[i][j] = 0.f;
        }

    if (fast) {
        // Exact: dist > 18 => expf(-dist) < 2^-25 => expf(e1/10) == 1.0f in fp32.
        #pragma unroll
        for (int mi = 0; mi < 4; mi++)
            #pragma unroll
            for (int ni = 0; ni < 4; ni++)
                #pragma unroll
                for (int r = 0; r < 4; r++) {
                    int ri = r >> 1, ci = r & 1;
                    if (rm2[mi][ri] == im2[ni][ci]) {
                        rowM[mi][ri] += 1.0f;
                        colM[ni][ci] += 1.0f;
                    }
                }
        #pragma unroll
        for (int i = 0; i < 4; i++) {
            rowS[i][0] = 8.0f; rowS[i][1] = 8.0f;
            colS[i][0] = 8.0f; colS[i][1] = 8.0f;
        }
    } else {
        #pragma unroll
        for (int mi = 0; mi < 4; mi++)
            #pragma unroll
            for (int ni = 0; ni < 4; ni++)
                #pragma unroll
                for (int r = 0; r < 4; r++) {
                    int ri = r >> 1, ci = r & 1;
                    float d = acc[mi][ni][r];
                    float logit = (d > 18.0f) ? 1.0f : __expf(__expf(-d) * 0.1f);
                    rowS[mi][ri] += logit;
                    colS[ni][ci] += logit;
                    if (rm2[mi][ri] == im2[ni][ci]) {
                        rowM[mi][ri] += logit;
                        colM[ni][ci] += logit;
                    }
                }
    }

    // Row reduce across tg: xor 1, 2.
    #pragma unroll
    for (int mi = 0; mi < 4; mi++)
        #pragma unroll
        for (int ri = 0; ri < 2; ri++) {
            float v = rowS[mi][ri], m = rowM[mi][ri];
            v += __shfl_xor_sync(0xffffffffu, v, 1);
            v += __shfl_xor_sync(0xffffffffu, v, 2);
            m += __shfl_xor_sync(0xffffffffu, m, 1);
            m += __shfl_xor_sync(0xffffffffu, m, 2);
            if (tg == 0) {
                int r = p0 + warp_m * 64 + mi * 16 + g + ri * 8;
                atomicAdd(&g_rowL [base + r], v);
                atomicAdd(&g_rowLM[base + r], m);
            }
        }

    // Col reduce across g: xor 4, 8, 16.
    #pragma unroll
    for (int ni = 0; ni < 4; ni++)
        #pragma unroll
        for (int ci = 0; ci < 2; ci++) {
            float v = colS[ni][ci], m = colM[ni][ci];
            v += __shfl_xor_sync(0xffffffffu, v, 4);
            v += __shfl_xor_sync(0xffffffffu, v, 8);
            v += __shfl_xor_sync(0xffffffffu, v, 16);
            m += __shfl_xor_sync(0xffffffffu, m, 4);
            m += __shfl_xor_sync(0xffffffffu, m, 8);
            m += __shfl_xor_sync(0xffffffffu, m, 16);
            if (g == 0) {
                int c = q0 + warp_n * 32 + ni * 8 + tg * 2 + ci;
                atomicAdd(&g_colL [base + c], v);
                atomicAdd(&g_colLM[base + c], m);
            }
        }
}

// ---------------------------------------------------------------------------
// finalize: masked -log mean -> scalar. One 1024-thread block.
// ---------------------------------------------------------------------------
__global__ __launch_bounds__(1024)
void finalize_kernel(const int* __restrict__ RM, const int* __restrict__ IM,
                     float* __restrict__ out)
{
    __shared__ float s_t[1024];
    __shared__ float s_c[1024];
    int tid = threadIdx.x;
    float tot = 0.f, cnt = 0.f;
    #pragma unroll
    for (int it = 0; it < NPIX / 1024; it++) {
        int j = it * 1024 + tid;
        {
            float l = g_rowL[j] + 1e-6f;
            float v = g_rowLM[j] / l;
            if (RM[j] > 0 && v != 0.0f) { tot -= __logf(v); cnt += 1.f; }
        }
        {
            float l = g_colL[j] + 1e-6f;
            float v = g_colLM[j] / l;
            if (IM[j] > 0 && v != 0.0f) { tot -= __logf(v); cnt += 1.f; }
        }
    }
    s_t[tid] = tot; s_c[tid] = cnt;
    __syncthreads();
    for (int s = 512; s > 0; s >>= 1) {
        if (tid < s) { s_t[tid] += s_t[tid + s]; s_c[tid] += s_c[tid + s]; }
        __syncthreads();
    }
    if (tid == 0) out[0] = s_t[0] / s_c[0];
}

// ---------------------------------------------------------------------------
extern "C" void kernel_launch(void* const* d_in, const int* in_sizes, int n_in,
                              void* d_out, int out_size)
{
    const float* R  = (const float*)d_in[0];   // rgb_map  (N,C,H,W) fp32
    const float* I  = (const float*)d_in[1];   // ir_map   (N,C,H,W) fp32
    const int*   RM = (const int*)  d_in[2];   // rgb_mask (N,H,W)   int32
    const int*   IM = (const int*)  d_in[3];   // ir_mask  (N,H,W)   int32
    float* out = (float*)d_out;

    prep_kernel<<<128, 256>>>(R, I);

    dim3 grid(HW / BN, HW / BM, NB);           // (8, 8, 8) = 512 CTAs
    tile_kernel<<<grid, 256>>>(RM, IM);

    finalize_kernel<<<1, 1024>>>(RM, IM, out);
}

// round 6
// speedup vs baseline: 1.6712x; 1.0658x over previous
#include <cuda_runtime.h>
#include <cuda_bf16.h>
#include <math.h>
#include <stdint.h>

// Problem shape (fixed): N=8, C=128, H=W=32 -> HW=1024.
#define NB   8
#define CC   128
#define HW   1024
#define BM   128
#define BN   128
#define BK   32            // pipeline chunk (4 chunks of 32 = CC)
#define NCHUNK (CC / BK)   // 4

#define NPIX (NB * HW)     // 8192

// ---------------------------------------------------------------------------
// Device scratch (allocation-free rule: __device__ globals)
// ---------------------------------------------------------------------------
__device__ __nv_bfloat16 g_Rbf[NB * CC * HW];
__device__ __nv_bfloat16 g_Ibf[NB * CC * HW];
__device__ float g_rnorm[NPIX];
__device__ float g_inorm[NPIX];
__device__ float g_rowL [NPIX];
__device__ float g_rowLM[NPIX];
__device__ float g_colL [NPIX];
__device__ float g_colLM[NPIX];

// ---------------------------------------------------------------------------
// PTX helpers
// ---------------------------------------------------------------------------
__device__ __forceinline__ uint32_t smem_u32(const void* p) {
    return (uint32_t)__cvta_generic_to_shared(p);
}

__device__ __forceinline__ void cp_async16(uint32_t dst, const void* src) {
    asm volatile("cp.async.cg.shared.global [%0], [%1], 16;" :: "r"(dst), "l"(src));
}
__device__ __forceinline__ void cp_commit() {
    asm volatile("cp.async.commit_group;");
}
template <int N>
__device__ __forceinline__ void cp_wait() {
    asm volatile("cp.async.wait_group %0;" :: "n"(N));
}

__device__ __forceinline__ void ldsm_x4_t(uint32_t& r0, uint32_t& r1,
                                          uint32_t& r2, uint32_t& r3, uint32_t addr) {
    asm volatile("ldmatrix.sync.aligned.m8n8.x4.trans.shared.b16 {%0,%1,%2,%3}, [%4];"
                 : "=r"(r0), "=r"(r1), "=r"(r2), "=r"(r3) : "r"(addr));
}

__device__ __forceinline__ void ldsm_x2_t(uint32_t& r0, uint32_t& r1, uint32_t addr) {
    asm volatile("ldmatrix.sync.aligned.m8n8.x2.trans.shared.b16 {%0,%1}, [%2];"
                 : "=r"(r0), "=r"(r1) : "r"(addr));
}

__device__ __forceinline__ void mma_bf16(float& d0, float& d1, float& d2, float& d3,
                                         uint32_t a0, uint32_t a1, uint32_t a2, uint32_t a3,
                                         uint32_t b0, uint32_t b1) {
    asm volatile("mma.sync.aligned.m16n8k16.row.col.f32.bf16.bf16.f32 "
                 "{%0,%1,%2,%3}, {%4,%5,%6,%7}, {%8,%9}, {%0,%1,%2,%3};"
                 : "+f"(d0), "+f"(d1), "+f"(d2), "+f"(d3)
                 : "r"(a0), "r"(a1), "r"(a2), "r"(a3), "r"(b0), "r"(b1));
}

// ---------------------------------------------------------------------------
// prep: norms (atomic-free) + fp32->bf16 convert + zero accumulators.
// 256 blocks x 256 threads: block b<128 handles rgb, b>=128 handles ir.
// Within a block: 64 pixels x 4 channel-quarters (32 ch each).
// ---------------------------------------------------------------------------
__global__ __launch_bounds__(256)
void prep_kernel(const float* __restrict__ R, const float* __restrict__ I)
{
    __shared__ float s_n[4][64];

    const int tid = threadIdx.x;
    const int bb  = blockIdx.x;
    const bool isR = bb < 128;
    const int blk = isR ? bb : bb - 128;
    const int px  = (blk << 6) + (tid & 63);   // global pixel 0..8191
    const int q   = tid >> 6;                  // channel quarter 0..3
    const int n   = px >> 10;
    const int p   = px & (HW - 1);

    const float* src = (isR ? R : I) + n * CC * HW + (q * 32) * HW + p;
    __nv_bfloat16* dst = (isR ? g_Rbf : g_Ibf) + n * CC * HW + (q * 32) * HW + p;

    float s = 0.f;
    #pragma unroll
    for (int c = 0; c < 32; c++) {
        float v = src[c * HW];
        dst[c * HW] = __float2bfloat16(v);
        s = fmaf(v, v, s);
    }
    s_n[q][tid & 63] = s;
    __syncthreads();

    if (tid < 64) {
        float t = s_n[0][tid] + s_n[1][tid] + s_n[2][tid] + s_n[3][tid];
        int px2 = (blk << 6) + tid;
        if (isR) g_rnorm[px2] = t; else g_inorm[px2] = t;
    }

    // Zero accumulators: 65536 threads cover 4 arrays x 8192 (first half).
    int idx = bb * 256 + tid;
    int arr = idx >> 13;
    int pos = idx & (NPIX - 1);
    if      (arr == 0) g_rowL [pos] = 0.f;
    else if (arr == 1) g_rowLM[pos] = 0.f;
    else if (arr == 2) g_colL [pos] = 0.f;
    else if (arr == 3) g_colLM[pos] = 0.f;
}

// ---------------------------------------------------------------------------
// fused bf16 tensor-core tile kernel: 128x128 (p,q) tile per CTA,
// cp.async 2-stage pipeline over 4 K-chunks of 32.
// ---------------------------------------------------------------------------
__global__ __launch_bounds__(256, 2)
void tile_kernel(const int* __restrict__ RM, const int* __restrict__ IM)
{
    __shared__ __nv_bfloat16 As[2][BK][BM + 8];
    __shared__ __nv_bfloat16 Bs[2][BK][BN + 8];

    const int n  = blockIdx.z;
    const int p0 = blockIdx.y * BM;
    const int q0 = blockIdx.x * BN;
    const int tid  = threadIdx.x;
    const int wid  = tid >> 5;
    const int lane = tid & 31;
    const int warp_m = wid >> 2;   // 0..1
    const int warp_n = wid & 3;    // 0..3

    const __nv_bfloat16* Rb = g_Rbf + n * CC * HW;
    const __nv_bfloat16* Ib = g_Ibf + n * CC * HW;

    // Per-stage staging: 32 rows x 16 uint4 per tensor = 512 uint4;
    // 2 per thread per tensor.
    const int f0  = tid;          // uint4 idx 0..255
    const int f1  = tid + 256;    // uint4 idx 256..511
    const int r0_ = f0 >> 4, c0_ = (f0 & 15) * 8;
    const int r1_ = f1 >> 4, c1_ = (f1 & 15) * 8;

    auto load_stage = [&](int st, int kk) {
        cp_async16(smem_u32(&As[st][r0_][c0_]), Rb + (kk + r0_) * HW + p0 + c0_);
        cp_async16(smem_u32(&As[st][r1_][c1_]), Rb + (kk + r1_) * HW + p0 + c1_);
        cp_async16(smem_u32(&Bs[st][r0_][c0_]), Ib + (kk + r0_) * HW + q0 + c0_);
        cp_async16(smem_u32(&Bs[st][r1_][c1_]), Ib + (kk + r1_) * HW + q0 + c1_);
    };

    float acc[4][4][4];
    #pragma unroll
    for (int mi = 0; mi < 4; mi++)
        #pragma unroll
        for (int ni = 0; ni < 4; ni++)
            #pragma unroll
            for (int r = 0; r < 4; r++)
                acc[mi][ni][r] = 0.f;

    const int sub   = lane >> 3;
    const int lrow  = lane & 7;
    const int a_kad = lrow + ((sub >> 1) ? 8 : 0);
    const int a_mad = warp_m * 64 + ((sub & 1) ? 8 : 0);
    const int b_kad = lrow + (((lane >> 3) & 1) ? 8 : 0);

    // Pipeline prologue: 2 stages in flight.
    load_stage(0, 0);
    cp_commit();
    load_stage(1, BK);
    cp_commit();

    #pragma unroll
    for (int c = 0; c < NCHUNK; c++) {
        const int st = c & 1;
        cp_wait<1>();            // oldest outstanding group done
        __syncthreads();

        #pragma unroll
        for (int ks = 0; ks < BK / 16; ks++) {
            const int k0 = ks * 16;
            uint32_t afr[4][4];
            #pragma unroll
            for (int mi = 0; mi < 4; mi++) {
                uint32_t addr = smem_u32(&As[st][k0 + a_kad][a_mad + mi * 16]);
                ldsm_x4_t(afr[mi][0], afr[mi][1], afr[mi][2], afr[mi][3], addr);
            }
            uint32_t bfr[4][2];
            #pragma unroll
            for (int ni = 0; ni < 4; ni++) {
                uint32_t addr = smem_u32(&Bs[st][k0 + b_kad][warp_n * 32 + ni * 8]);
                ldsm_x2_t(bfr[ni][0], bfr[ni][1], addr);
            }
            #pragma unroll
            for (int mi = 0; mi < 4; mi++)
                #pragma unroll
                for (int ni = 0; ni < 4; ni++)
                    mma_bf16(acc[mi][ni][0], acc[mi][ni][1], acc[mi][ni][2], acc[mi][ni][3],
                             afr[mi][0], afr[mi][1], afr[mi][2], afr[mi][3],
                             bfr[ni][0], bfr[ni][1]);
        }
        __syncthreads();         // everyone done reading stage st
        if (c + 2 < NCHUNK)
            load_stage(st, (c + 2) * BK);
        cp_commit();             // commit (possibly empty) group to keep counts aligned
    }

    // --------------------------- fused epilogue ---------------------------
    const int g  = lane >> 2;
    const int tg = lane & 3;
    const int base = n * HW;

    float rn2[4][2]; int rm2[4][2];
    #pragma unroll
    for (int mi = 0; mi < 4; mi++) {
        int r = p0 + warp_m * 64 + mi * 16 + g;
        rn2[mi][0] = g_rnorm[base + r];     rm2[mi][0] = RM[base + r];
        rn2[mi][1] = g_rnorm[base + r + 8]; rm2[mi][1] = RM[base + r + 8];
    }
    float in2[4][2]; int im2[4][2];
    #pragma unroll
    for (int ni = 0; ni < 4; ni++) {
        int c = q0 + warp_n * 32 + ni * 8 + tg * 2;
        in2[ni][0] = g_inorm[base + c];     im2[ni][0] = IM[base + c];
        in2[ni][1] = g_inorm[base + c + 1]; im2[ni][1] = IM[base + c + 1];
    }

    // acc -> dist in place; thread-local min, then WARP-UNIFORM vote.
    float mind = 1e30f;
    #pragma unroll
    for (int mi = 0; mi < 4; mi++)
        #pragma unroll
        for (int ni = 0; ni < 4; ni++)
            #pragma unroll
            for (int r = 0; r < 4; r++) {
                float d = rn2[mi][r >> 1] + in2[ni][r & 1] - 2.0f * acc[mi][ni][r];
                acc[mi][ni][r] = d;
                mind = fminf(mind, d);
            }
    const bool fast = __all_sync(0xffffffffu, mind > 18.0f);

    float rowS[4][2], rowM[4][2], colS[4][2], colM[4][2];
    #pragma unroll
    for (int i = 0; i < 4; i++)
        #pragma unroll
        for (int j = 0; j < 2; j++) {
            rowS[i][j] = 0.f; rowM[i][j] = 0.f;
            colS[i][j] = 0.f; colM[i][j] = 0.f;
        }

    if (fast) {
        // Exact: dist > 18 => expf(-dist) < 2^-25 => expf(e1/10) == 1.0f in fp32.
        #pragma unroll
        for (int mi = 0; mi < 4; mi++)
            #pragma unroll
            for (int ni = 0; ni < 4; ni++)
                #pragma unroll
                for (int r = 0; r < 4; r++) {
                    int ri = r >> 1, ci = r & 1;
                    if (rm2[mi][ri] == im2[ni][ci]) {
                        rowM[mi][ri] += 1.0f;
                        colM[ni][ci] += 1.0f;
                    }
                }
        #pragma unroll
        for (int i = 0; i < 4; i++) {
            rowS[i][0] = 8.0f; rowS[i][1] = 8.0f;
            colS[i][0] = 8.0f; colS[i][1] = 8.0f;
        }
    } else {
        #pragma unroll
        for (int mi = 0; mi < 4; mi++)
            #pragma unroll
            for (int ni = 0; ni < 4; ni++)
                #pragma unroll
                for (int r = 0; r < 4; r++) {
                    int ri = r >> 1, ci = r & 1;
                    float d = acc[mi][ni][r];
                    float logit = (d > 18.0f) ? 1.0f : __expf(__expf(-d) * 0.1f);
                    rowS[mi][ri] += logit;
                    colS[ni][ci] += logit;
                    if (rm2[mi][ri] == im2[ni][ci]) {
                        rowM[mi][ri] += logit;
                        colM[ni][ci] += logit;
                    }
                }
    }

    // Row reduce across tg: xor 1, 2.
    #pragma unroll
    for (int mi = 0; mi < 4; mi++)
        #pragma unroll
        for (int ri = 0; ri < 2; ri++) {
            float v = rowS[mi][ri], m = rowM[mi][ri];
            v += __shfl_xor_sync(0xffffffffu, v, 1);
            v += __shfl_xor_sync(0xffffffffu, v, 2);
            m += __shfl_xor_sync(0xffffffffu, m, 1);
            m += __shfl_xor_sync(0xffffffffu, m, 2);
            if (tg == 0) {
                int r = p0 + warp_m * 64 + mi * 16 + g + ri * 8;
                atomicAdd(&g_rowL [base + r], v);
                atomicAdd(&g_rowLM[base + r], m);
            }
        }

    // Col reduce across g: xor 4, 8, 16.
    #pragma unroll
    for (int ni = 0; ni < 4; ni++)
        #pragma unroll
        for (int ci = 0; ci < 2; ci++) {
            float v = colS[ni][ci], m = colM[ni][ci];
            v += __shfl_xor_sync(0xffffffffu, v, 4);
            v += __shfl_xor_sync(0xffffffffu, v, 8);
            v += __shfl_xor_sync(0xffffffffu, v, 16);
            m += __shfl_xor_sync(0xffffffffu, m, 4);
            m += __shfl_xor_sync(0xffffffffu, m, 8);
            m += __shfl_xor_sync(0xffffffffu, m, 16);
            if (g == 0) {
                int c = q0 + warp_n * 32 + ni * 8 + tg * 2 + ci;
                atomicAdd(&g_colL [base + c], v);
                atomicAdd(&g_colLM[base + c], m);
            }
        }
}

// ---------------------------------------------------------------------------
// finalize: masked -log mean -> scalar. One 1024-thread block.
// ---------------------------------------------------------------------------
__global__ __launch_bounds__(1024)
void finalize_kernel(const int* __restrict__ RM, const int* __restrict__ IM,
                     float* __restrict__ out)
{
    __shared__ float s_t[1024];
    __shared__ float s_c[1024];
    int tid = threadIdx.x;
    float tot = 0.f, cnt = 0.f;
    #pragma unroll
    for (int it = 0; it < NPIX / 1024; it++) {
        int j = it * 1024 + tid;
        {
            float l = g_rowL[j] + 1e-6f;
            float v = g_rowLM[j] / l;
            if (RM[j] > 0 && v != 0.0f) { tot -= __logf(v); cnt += 1.f; }
        }
        {
            float l = g_colL[j] + 1e-6f;
            float v = g_colLM[j] / l;
            if (IM[j] > 0 && v != 0.0f) { tot -= __logf(v); cnt += 1.f; }
        }
    }
    s_t[tid] = tot; s_c[tid] = cnt;
    __syncthreads();
    for (int s = 512; s > 0; s >>= 1) {
        if (tid < s) { s_t[tid] += s_t[tid + s]; s_c[tid] += s_c[tid + s]; }
        __syncthreads();
    }
    if (tid == 0) out[0] = s_t[0] / s_c[0];
}

// ---------------------------------------------------------------------------
extern "C" void kernel_launch(void* const* d_in, const int* in_sizes, int n_in,
                              void* d_out, int out_size)
{
    const float* R  = (const float*)d_in[0];   // rgb_map  (N,C,H,W) fp32
    const float* I  = (const float*)d_in[1];   // ir_map   (N,C,H,W) fp32
    const int*   RM = (const int*)  d_in[2];   // rgb_mask (N,H,W)   int32
    const int*   IM = (const int*)  d_in[3];   // ir_mask  (N,H,W)   int32
    float* out = (float*)d_out;

    prep_kernel<<<256, 256>>>(R, I);

    dim3 grid(HW / BN, HW / BM, NB);           // (8, 8, 8) = 512 CTAs
    tile_kernel<<<grid, 256>>>(RM, IM);

    finalize_kernel<<<1, 1024>>>(RM, IM, out);
}

// round 7
// speedup vs baseline: 2.0765x; 1.2425x over previous
#include <cuda_runtime.h>
#include <cuda_bf16.h>
#include <math.h>
#include <stdint.h>

// Problem shape (fixed): N=8, C=128, H=W=32 -> HW=1024.
#define NB   8
#define CC   128
#define HW   1024
#define BM   128
#define BN   128
#define BK   32            // pipeline chunk (4 chunks of 32 = CC)
#define NCHUNK (CC / BK)   // 4

#define NPIX (NB * HW)     // 8192

// ---------------------------------------------------------------------------
// Device scratch (allocation-free rule: __device__ globals)
// ---------------------------------------------------------------------------
__device__ __nv_bfloat16 g_Rbf[NB * CC * HW];
__device__ __nv_bfloat16 g_Ibf[NB * CC * HW];
__device__ float g_rnorm[NPIX];
__device__ float g_inorm[NPIX];
__device__ float g_rowL [NPIX];
__device__ float g_rowLM[NPIX];
__device__ float g_colL [NPIX];
__device__ float g_colLM[NPIX];
__device__ float g_tot;
__device__ float g_cnt;

// ---------------------------------------------------------------------------
// PTX helpers
// ---------------------------------------------------------------------------
__device__ __forceinline__ uint32_t smem_u32(const void* p) {
    return (uint32_t)__cvta_generic_to_shared(p);
}

__device__ __forceinline__ void cp_async16(uint32_t dst, const void* src) {
    asm volatile("cp.async.cg.shared.global [%0], [%1], 16;" :: "r"(dst), "l"(src));
}
__device__ __forceinline__ void cp_commit() {
    asm volatile("cp.async.commit_group;");
}
template <int N>
__device__ __forceinline__ void cp_wait() {
    asm volatile("cp.async.wait_group %0;" :: "n"(N));
}

__device__ __forceinline__ void ldsm_x4_t(uint32_t& r0, uint32_t& r1,
                                          uint32_t& r2, uint32_t& r3, uint32_t addr) {
    asm volatile("ldmatrix.sync.aligned.m8n8.x4.trans.shared.b16 {%0,%1,%2,%3}, [%4];"
                 : "=r"(r0), "=r"(r1), "=r"(r2), "=r"(r3) : "r"(addr));
}

__device__ __forceinline__ void ldsm_x2_t(uint32_t& r0, uint32_t& r1, uint32_t addr) {
    asm volatile("ldmatrix.sync.aligned.m8n8.x2.trans.shared.b16 {%0,%1}, [%2];"
                 : "=r"(r0), "=r"(r1) : "r"(addr));
}

__device__ __forceinline__ void mma_bf16(float& d0, float& d1, float& d2, float& d3,
                                         uint32_t a0, uint32_t a1, uint32_t a2, uint32_t a3,
                                         uint32_t b0, uint32_t b1) {
    asm volatile("mma.sync.aligned.m16n8k16.row.col.f32.bf16.bf16.f32 "
                 "{%0,%1,%2,%3}, {%4,%5,%6,%7}, {%8,%9}, {%0,%1,%2,%3};"
                 : "+f"(d0), "+f"(d1), "+f"(d2), "+f"(d3)
                 : "r"(a0), "r"(a1), "r"(a2), "r"(a3), "r"(b0), "r"(b1));
}

// ---------------------------------------------------------------------------
// prep v3: float4-vectorized norms + fp32->bf16 convert + zero accumulators.
// 512 blocks x 256 threads: block bb<256 -> rgb, else ir; blk = bb & 255.
// Block covers 32 pixels x 128 channels. Thread: pix4 = tid&7 (4 pixels),
// grp = tid>>3 (4 channels each).
// ---------------------------------------------------------------------------
__global__ __launch_bounds__(256)
void prep_kernel(const float* __restrict__ R, const float* __restrict__ I)
{
    __shared__ float4 s_n[32][8];
    __shared__ float4 s_p[8][8];

    const int tid = threadIdx.x;
    const int bb  = blockIdx.x;
    const bool isR = bb < 256;
    const int blk = bb & 255;
    const int pix4 = tid & 7;        // which group of 4 pixels
    const int grp  = tid >> 3;       // channel group 0..31 (4 ch each)
    const int px0  = blk * 32 + pix4 * 4;   // first of 4 pixels
    const int n    = px0 >> 10;
    const int p    = px0 & (HW - 1);

    const float* src = (isR ? R : I) + n * CC * HW + p;
    __nv_bfloat16* dst = (isR ? g_Rbf : g_Ibf) + n * CC * HW + p;

    float4 s = make_float4(0.f, 0.f, 0.f, 0.f);
    #pragma unroll
    for (int i = 0; i < 4; i++) {
        int c = grp * 4 + i;
        float4 v = *reinterpret_cast<const float4*>(src + c * HW);
        __nv_bfloat162 h0 = __floats2bfloat162_rn(v.x, v.y);
        __nv_bfloat162 h1 = __floats2bfloat162_rn(v.z, v.w);
        uint2 u;
        u.x = *reinterpret_cast<uint32_t*>(&h0);
        u.y = *reinterpret_cast<uint32_t*>(&h1);
        *reinterpret_cast<uint2*>(dst + c * HW) = u;
        s.x = fmaf(v.x, v.x, s.x);
        s.y = fmaf(v.y, v.y, s.y);
        s.z = fmaf(v.z, v.z, s.z);
        s.w = fmaf(v.w, v.w, s.w);
    }
    s_n[grp][pix4] = s;
    __syncthreads();

    if (tid < 64) {
        int pj = tid & 7, h = tid >> 3;       // 8 quartets of groups
        float4 a = s_n[h * 4 + 0][pj];
        float4 b = s_n[h * 4 + 1][pj];
        float4 c = s_n[h * 4 + 2][pj];
        float4 d = s_n[h * 4 + 3][pj];
        s_p[h][pj] = make_float4(a.x + b.x + c.x + d.x, a.y + b.y + c.y + d.y,
                                 a.z + b.z + c.z + d.z, a.w + b.w + c.w + d.w);
    }
    __syncthreads();
    if (tid < 8) {
        float4 t = make_float4(0.f, 0.f, 0.f, 0.f);
        #pragma unroll
        for (int h = 0; h < 8; h++) {
            float4 v = s_p[h][tid];
            t.x += v.x; t.y += v.y; t.z += v.z; t.w += v.w;
        }
        float* np = (isR ? g_rnorm : g_inorm) + blk * 32 + tid * 4;
        *reinterpret_cast<float4*>(np) = t;
    }

    // Zero accumulators: first 32768 global threads cover 4 arrays x 8192.
    int idx = bb * 256 + tid;
    if (idx < 4 * NPIX) {
        int arr = idx >> 13;
        int pos = idx & (NPIX - 1);
        if      (arr == 0) g_rowL [pos] = 0.f;
        else if (arr == 1) g_rowLM[pos] = 0.f;
        else if (arr == 2) g_colL [pos] = 0.f;
        else               g_colLM[pos] = 0.f;
    }
    if (idx == 0) { g_tot = 0.f; g_cnt = 0.f; }
}

// ---------------------------------------------------------------------------
// fused bf16 tensor-core tile kernel: 128x128 (p,q) tile per CTA,
// cp.async 2-stage pipeline over 4 K-chunks of 32. (unchanged from R6)
// ---------------------------------------------------------------------------
__global__ __launch_bounds__(256, 2)
void tile_kernel(const int* __restrict__ RM, const int* __restrict__ IM)
{
    __shared__ __nv_bfloat16 As[2][BK][BM + 8];
    __shared__ __nv_bfloat16 Bs[2][BK][BN + 8];

    const int n  = blockIdx.z;
    const int p0 = blockIdx.y * BM;
    const int q0 = blockIdx.x * BN;
    const int tid  = threadIdx.x;
    const int wid  = tid >> 5;
    const int lane = tid & 31;
    const int warp_m = wid >> 2;   // 0..1
    const int warp_n = wid & 3;    // 0..3

    const __nv_bfloat16* Rb = g_Rbf + n * CC * HW;
    const __nv_bfloat16* Ib = g_Ibf + n * CC * HW;

    const int f0  = tid;          // uint4 idx 0..255
    const int f1  = tid + 256;    // uint4 idx 256..511
    const int r0_ = f0 >> 4, c0_ = (f0 & 15) * 8;
    const int r1_ = f1 >> 4, c1_ = (f1 & 15) * 8;

    auto load_stage = [&](int st, int kk) {
        cp_async16(smem_u32(&As[st][r0_][c0_]), Rb + (kk + r0_) * HW + p0 + c0_);
        cp_async16(smem_u32(&As[st][r1_][c1_]), Rb + (kk + r1_) * HW + p0 + c1_);
        cp_async16(smem_u32(&Bs[st][r0_][c0_]), Ib + (kk + r0_) * HW + q0 + c0_);
        cp_async16(smem_u32(&Bs[st][r1_][c1_]), Ib + (kk + r1_) * HW + q0 + c1_);
    };

    float acc[4][4][4];
    #pragma unroll
    for (int mi = 0; mi < 4; mi++)
        #pragma unroll
        for (int ni = 0; ni < 4; ni++)
            #pragma unroll
            for (int r = 0; r < 4; r++)
                acc[mi][ni][r] = 0.f;

    const int sub   = lane >> 3;
    const int lrow  = lane & 7;
    const int a_kad = lrow + ((sub >> 1) ? 8 : 0);
    const int a_mad = warp_m * 64 + ((sub & 1) ? 8 : 0);
    const int b_kad = lrow + (((lane >> 3) & 1) ? 8 : 0);

    load_stage(0, 0);
    cp_commit();
    load_stage(1, BK);
    cp_commit();

    #pragma unroll
    for (int c = 0; c < NCHUNK; c++) {
        const int st = c & 1;
        cp_wait<1>();
        __syncthreads();

        #pragma unroll
        for (int ks = 0; ks < BK / 16; ks++) {
            const int k0 = ks * 16;
            uint32_t afr[4][4];
            #pragma unroll
            for (int mi = 0; mi < 4; mi++) {
                uint32_t addr = smem_u32(&As[st][k0 + a_kad][a_mad + mi * 16]);
                ldsm_x4_t(afr[mi][0], afr[mi][1], afr[mi][2], afr[mi][3], addr);
            }
            uint32_t bfr[4][2];
            #pragma unroll
            for (int ni = 0; ni < 4; ni++) {
                uint32_t addr = smem_u32(&Bs[st][k0 + b_kad][warp_n * 32 + ni * 8]);
                ldsm_x2_t(bfr[ni][0], bfr[ni][1], addr);
            }
            #pragma unroll
            for (int mi = 0; mi < 4; mi++)
                #pragma unroll
                for (int ni = 0; ni < 4; ni++)
                    mma_bf16(acc[mi][ni][0], acc[mi][ni][1], acc[mi][ni][2], acc[mi][ni][3],
                             afr[mi][0], afr[mi][1], afr[mi][2], afr[mi][3],
                             bfr[ni][0], bfr[ni][1]);
        }
        __syncthreads();
        if (c + 2 < NCHUNK)
            load_stage(st, (c + 2) * BK);
        cp_commit();
    }

    // --------------------------- fused epilogue ---------------------------
    const int g  = lane >> 2;
    const int tg = lane & 3;
    const int base = n * HW;

    float rn2[4][2]; int rm2[4][2];
    #pragma unroll
    for (int mi = 0; mi < 4; mi++) {
        int r = p0 + warp_m * 64 + mi * 16 + g;
        rn2[mi][0] = g_rnorm[base + r];     rm2[mi][0] = RM[base + r];
        rn2[mi][1] = g_rnorm[base + r + 8]; rm2[mi][1] = RM[base + r + 8];
    }
    float in2[4][2]; int im2[4][2];
    #pragma unroll
    for (int ni = 0; ni < 4; ni++) {
        int c = q0 + warp_n * 32 + ni * 8 + tg * 2;
        in2[ni][0] = g_inorm[base + c];     im2[ni][0] = IM[base + c];
        in2[ni][1] = g_inorm[base + c + 1]; im2[ni][1] = IM[base + c + 1];
    }

    float mind = 1e30f;
    #pragma unroll
    for (int mi = 0; mi < 4; mi++)
        #pragma unroll
        for (int ni = 0; ni < 4; ni++)
            #pragma unroll
            for (int r = 0; r < 4; r++) {
                float d = rn2[mi][r >> 1] + in2[ni][r & 1] - 2.0f * acc[mi][ni][r];
                acc[mi][ni][r] = d;
                mind = fminf(mind, d);
            }
    const bool fast = __all_sync(0xffffffffu, mind > 18.0f);

    float rowS[4][2], rowM[4][2], colS[4][2], colM[4][2];
    #pragma unroll
    for (int i = 0; i < 4; i++)
        #pragma unroll
        for (int j = 0; j < 2; j++) {
            rowS[i][j] = 0.f; rowM[i][j] = 0.f;
            colS[i][j] = 0.f; colM[i][j] = 0.f;
        }

    if (fast) {
        // Exact: dist > 18 => expf(-dist) < 2^-25 => expf(e1/10) == 1.0f in fp32.
        #pragma unroll
        for (int mi = 0; mi < 4; mi++)
            #pragma unroll
            for (int ni = 0; ni < 4; ni++)
                #pragma unroll
                for (int r = 0; r < 4; r++) {
                    int ri = r >> 1, ci = r & 1;
                    if (rm2[mi][ri] == im2[ni][ci]) {
                        rowM[mi][ri] += 1.0f;
                        colM[ni][ci] += 1.0f;
                    }
                }
        #pragma unroll
        for (int i = 0; i < 4; i++) {
            rowS[i][0] = 8.0f; rowS[i][1] = 8.0f;
            colS[i][0] = 8.0f; colS[i][1] = 8.0f;
        }
    } else {
        #pragma unroll
        for (int mi = 0; mi < 4; mi++)
            #pragma unroll
            for (int ni = 0; ni < 4; ni++)
                #pragma unroll
                for (int r = 0; r < 4; r++) {
                    int ri = r >> 1, ci = r & 1;
                    float d = acc[mi][ni][r];
                    float logit = (d > 18.0f) ? 1.0f : __expf(__expf(-d) * 0.1f);
                    rowS[mi][ri] += logit;
                    colS[ni][ci] += logit;
                    if (rm2[mi][ri] == im2[ni][ci]) {
                        rowM[mi][ri] += logit;
                        colM[ni][ci] += logit;
                    }
                }
    }

    // Row reduce across tg: xor 1, 2.
    #pragma unroll
    for (int mi = 0; mi < 4; mi++)
        #pragma unroll
        for (int ri = 0; ri < 2; ri++) {
            float v = rowS[mi][ri], m = rowM[mi][ri];
            v += __shfl_xor_sync(0xffffffffu, v, 1);
            v += __shfl_xor_sync(0xffffffffu, v, 2);
            m += __shfl_xor_sync(0xffffffffu, m, 1);
            m += __shfl_xor_sync(0xffffffffu, m, 2);
            if (tg == 0) {
                int r = p0 + warp_m * 64 + mi * 16 + g + ri * 8;
                atomicAdd(&g_rowL [base + r], v);
                atomicAdd(&g_rowLM[base + r], m);
            }
        }

    // Col reduce across g: xor 4, 8, 16.
    #pragma unroll
    for (int ni = 0; ni < 4; ni++)
        #pragma unroll
        for (int ci = 0; ci < 2; ci++) {
            float v = colS[ni][ci], m = colM[ni][ci];
            v += __shfl_xor_sync(0xffffffffu, v, 4);
            v += __shfl_xor_sync(0xffffffffu, v, 8);
            v += __shfl_xor_sync(0xffffffffu, v, 16);
            m += __shfl_xor_sync(0xffffffffu, m, 4);
            m += __shfl_xor_sync(0xffffffffu, m, 8);
            m += __shfl_xor_sync(0xffffffffu, m, 16);
            if (g == 0) {
                int c = q0 + warp_n * 32 + ni * 8 + tg * 2 + ci;
                atomicAdd(&g_colL [base + c], v);
                atomicAdd(&g_colLM[base + c], m);
            }
        }
}

// ---------------------------------------------------------------------------
// reduce: masked -log sums across 64 blocks -> g_tot/g_cnt (MUFU parallel)
// ---------------------------------------------------------------------------
__global__ __launch_bounds__(256)
void reduce_kernel(const int* __restrict__ RM, const int* __restrict__ IM)
{
    __shared__ float s_t[256];
    __shared__ float s_c[256];
    int tid = threadIdx.x;
    int j = blockIdx.x * 128 + (tid & 127);      // 64 blocks x 128 = 8192
    bool isRow = tid < 128;

    float tot = 0.f, cnt = 0.f;
    if (isRow) {
        float l = g_rowL[j] + 1e-6f;
        float v = g_rowLM[j] / l;
        if (RM[j] > 0 && v != 0.0f) { tot = -__logf(v); cnt = 1.f; }
    } else {
        float l = g_colL[j] + 1e-6f;
        float v = g_colLM[j] / l;
        if (IM[j] > 0 && v != 0.0f) { tot = -__logf(v); cnt = 1.f; }
    }
    s_t[tid] = tot; s_c[tid] = cnt;
    __syncthreads();
    for (int s = 128; s > 0; s >>= 1) {
        if (tid < s) { s_t[tid] += s_t[tid + s]; s_c[tid] += s_c[tid + s]; }
        __syncthreads();
    }
    if (tid == 0) {
        atomicAdd(&g_tot, s_t[0]);
        atomicAdd(&g_cnt, s_c[0]);
    }
}

__global__ void div_kernel(float* __restrict__ out)
{
    out[0] = g_tot / g_cnt;
}

// ---------------------------------------------------------------------------
extern "C" void kernel_launch(void* const* d_in, const int* in_sizes, int n_in,
                              void* d_out, int out_size)
{
    const float* R  = (const float*)d_in[0];   // rgb_map  (N,C,H,W) fp32
    const float* I  = (const float*)d_in[1];   // ir_map   (N,C,H,W) fp32
    const int*   RM = (const int*)  d_in[2];   // rgb_mask (N,H,W)   int32
    const int*   IM = (const int*)  d_in[3];   // ir_mask  (N,H,W)   int32
    float* out = (float*)d_out;

    prep_kernel<<<512, 256>>>(R, I);

    dim3 grid(HW / BN, HW / BM, NB);           // (8, 8, 8) = 512 CTAs
    tile_kernel<<<grid, 256>>>(RM, IM);

    reduce_kernel<<<64, 256>>>(RM, IM);
    div_kernel<<<1, 1>>>(out);
}

// round 8
// speedup vs baseline: 2.0846x; 1.0039x over previous
#include <cuda_runtime.h>
#include <cuda_bf16.h>
#include <math.h>
#include <stdint.h>

// Problem shape (fixed): N=8, C=128, H=W=32 -> HW=1024.
#define NB   8
#define CC   128
#define HW   1024
#define BM   128
#define BN   128
#define BK   32            // pipeline chunk (4 chunks of 32 = CC)
#define NCHUNK (CC / BK)   // 4

#define NPIX (NB * HW)     // 8192
#define RBLK 64            // reduce grid

// ---------------------------------------------------------------------------
// Device scratch (allocation-free rule: __device__ globals)
// ---------------------------------------------------------------------------
__device__ __nv_bfloat16 g_Rbf[NB * CC * HW];
__device__ __nv_bfloat16 g_Ibf[NB * CC * HW];
__device__ float g_rnorm[NPIX];
__device__ float g_inorm[NPIX];
__device__ float g_rowL [NPIX];
__device__ float g_rowLM[NPIX];
__device__ float g_colL [NPIX];
__device__ float g_colLM[NPIX];
__device__ float g_tot;
__device__ float g_cnt;
__device__ unsigned int g_rctr;

// ---------------------------------------------------------------------------
// PTX helpers
// ---------------------------------------------------------------------------
__device__ __forceinline__ uint32_t smem_u32(const void* p) {
    return (uint32_t)__cvta_generic_to_shared(p);
}

__device__ __forceinline__ void cp_async16(uint32_t dst, const void* src) {
    asm volatile("cp.async.cg.shared.global [%0], [%1], 16;" :: "r"(dst), "l"(src));
}
__device__ __forceinline__ void cp_commit() {
    asm volatile("cp.async.commit_group;");
}
template <int N>
__device__ __forceinline__ void cp_wait() {
    asm volatile("cp.async.wait_group %0;" :: "n"(N));
}

__device__ __forceinline__ void ldsm_x4_t(uint32_t& r0, uint32_t& r1,
                                          uint32_t& r2, uint32_t& r3, uint32_t addr) {
    asm volatile("ldmatrix.sync.aligned.m8n8.x4.trans.shared.b16 {%0,%1,%2,%3}, [%4];"
                 : "=r"(r0), "=r"(r1), "=r"(r2), "=r"(r3) : "r"(addr));
}

__device__ __forceinline__ void ldsm_x2_t(uint32_t& r0, uint32_t& r1, uint32_t addr) {
    asm volatile("ldmatrix.sync.aligned.m8n8.x2.trans.shared.b16 {%0,%1}, [%2];"
                 : "=r"(r0), "=r"(r1) : "r"(addr));
}

__device__ __forceinline__ void mma_bf16(float& d0, float& d1, float& d2, float& d3,
                                         uint32_t a0, uint32_t a1, uint32_t a2, uint32_t a3,
                                         uint32_t b0, uint32_t b1) {
    asm volatile("mma.sync.aligned.m16n8k16.row.col.f32.bf16.bf16.f32 "
                 "{%0,%1,%2,%3}, {%4,%5,%6,%7}, {%8,%9}, {%0,%1,%2,%3};"
                 : "+f"(d0), "+f"(d1), "+f"(d2), "+f"(d3)
                 : "r"(a0), "r"(a1), "r"(a2), "r"(a3), "r"(b0), "r"(b1));
}

// ---------------------------------------------------------------------------
// prep v3: float4-vectorized norms + fp32->bf16 convert + zero accumulators.
// 512 blocks x 256 threads: block bb<256 -> rgb, else ir; blk = bb & 255.
// ---------------------------------------------------------------------------
__global__ __launch_bounds__(256)
void prep_kernel(const float* __restrict__ R, const float* __restrict__ I)
{
    __shared__ float4 s_n[32][8];
    __shared__ float4 s_p[8][8];

    const int tid = threadIdx.x;
    const int bb  = blockIdx.x;
    const bool isR = bb < 256;
    const int blk = bb & 255;
    const int pix4 = tid & 7;        // which group of 4 pixels
    const int grp  = tid >> 3;       // channel group 0..31 (4 ch each)
    const int px0  = blk * 32 + pix4 * 4;   // first of 4 pixels
    const int n    = px0 >> 10;
    const int p    = px0 & (HW - 1);

    const float* src = (isR ? R : I) + n * CC * HW + p;
    __nv_bfloat16* dst = (isR ? g_Rbf : g_Ibf) + n * CC * HW + p;

    float4 s = make_float4(0.f, 0.f, 0.f, 0.f);
    #pragma unroll
    for (int i = 0; i < 4; i++) {
        int c = grp * 4 + i;
        float4 v = *reinterpret_cast<const float4*>(src + c * HW);
        __nv_bfloat162 h0 = __floats2bfloat162_rn(v.x, v.y);
        __nv_bfloat162 h1 = __floats2bfloat162_rn(v.z, v.w);
        uint2 u;
        u.x = *reinterpret_cast<uint32_t*>(&h0);
        u.y = *reinterpret_cast<uint32_t*>(&h1);
        *reinterpret_cast<uint2*>(dst + c * HW) = u;
        s.x = fmaf(v.x, v.x, s.x);
        s.y = fmaf(v.y, v.y, s.y);
        s.z = fmaf(v.z, v.z, s.z);
        s.w = fmaf(v.w, v.w, s.w);
    }
    s_n[grp][pix4] = s;
    __syncthreads();

    if (tid < 64) {
        int pj = tid & 7, h = tid >> 3;
        float4 a = s_n[h * 4 + 0][pj];
        float4 b = s_n[h * 4 + 1][pj];
        float4 c = s_n[h * 4 + 2][pj];
        float4 d = s_n[h * 4 + 3][pj];
        s_p[h][pj] = make_float4(a.x + b.x + c.x + d.x, a.y + b.y + c.y + d.y,
                                 a.z + b.z + c.z + d.z, a.w + b.w + c.w + d.w);
    }
    __syncthreads();
    if (tid < 8) {
        float4 t = make_float4(0.f, 0.f, 0.f, 0.f);
        #pragma unroll
        for (int h = 0; h < 8; h++) {
            float4 v = s_p[h][tid];
            t.x += v.x; t.y += v.y; t.z += v.z; t.w += v.w;
        }
        float* np = (isR ? g_rnorm : g_inorm) + blk * 32 + tid * 4;
        *reinterpret_cast<float4*>(np) = t;
    }

    // Zero accumulators: first 32768 global threads cover 4 arrays x 8192.
    int idx = bb * 256 + tid;
    if (idx < 4 * NPIX) {
        int arr = idx >> 13;
        int pos = idx & (NPIX - 1);
        if      (arr == 0) g_rowL [pos] = 0.f;
        else if (arr == 1) g_rowLM[pos] = 0.f;
        else if (arr == 2) g_colL [pos] = 0.f;
        else               g_colLM[pos] = 0.f;
    }
    if (idx == 0) { g_tot = 0.f; g_cnt = 0.f; g_rctr = 0u; }
}

// ---------------------------------------------------------------------------
// fused bf16 tensor-core tile kernel: 128x128 (p,q) tile per CTA,
// cp.async 2-stage pipeline over 4 K-chunks of 32.
// ---------------------------------------------------------------------------
__global__ __launch_bounds__(256, 2)
void tile_kernel(const int* __restrict__ RM, const int* __restrict__ IM)
{
    __shared__ __nv_bfloat16 As[2][BK][BM + 8];
    __shared__ __nv_bfloat16 Bs[2][BK][BN + 8];

    const int n  = blockIdx.z;
    const int p0 = blockIdx.y * BM;
    const int q0 = blockIdx.x * BN;
    const int tid  = threadIdx.x;
    const int wid  = tid >> 5;
    const int lane = tid & 31;
    const int warp_m = wid >> 2;   // 0..1
    const int warp_n = wid & 3;    // 0..3

    const __nv_bfloat16* Rb = g_Rbf + n * CC * HW;
    const __nv_bfloat16* Ib = g_Ibf + n * CC * HW;

    const int f0  = tid;          // uint4 idx 0..255
    const int f1  = tid + 256;    // uint4 idx 256..511
    const int r0_ = f0 >> 4, c0_ = (f0 & 15) * 8;
    const int r1_ = f1 >> 4, c1_ = (f1 & 15) * 8;

    auto load_stage = [&](int st, int kk) {
        cp_async16(smem_u32(&As[st][r0_][c0_]), Rb + (kk + r0_) * HW + p0 + c0_);
        cp_async16(smem_u32(&As[st][r1_][c1_]), Rb + (kk + r1_) * HW + p0 + c1_);
        cp_async16(smem_u32(&Bs[st][r0_][c0_]), Ib + (kk + r0_) * HW + q0 + c0_);
        cp_async16(smem_u32(&Bs[st][r1_][c1_]), Ib + (kk + r1_) * HW + q0 + c1_);
    };

    float acc[4][4][4];
    #pragma unroll
    for (int mi = 0; mi < 4; mi++)
        #pragma unroll
        for (int ni = 0; ni < 4; ni++)
            #pragma unroll
            for (int r = 0; r < 4; r++)
                acc[mi][ni][r] = 0.f;

    const int sub   = lane >> 3;
    const int lrow  = lane & 7;
    const int a_kad = lrow + ((sub >> 1) ? 8 : 0);
    const int a_mad = warp_m * 64 + ((sub & 1) ? 8 : 0);
    const int b_kad = lrow + (((lane >> 3) & 1) ? 8 : 0);

    load_stage(0, 0);
    cp_commit();
    load_stage(1, BK);
    cp_commit();

    #pragma unroll
    for (int c = 0; c < NCHUNK; c++) {
        const int st = c & 1;
        cp_wait<1>();
        __syncthreads();

        #pragma unroll
        for (int ks = 0; ks < BK / 16; ks++) {
            const int k0 = ks * 16;
            uint32_t afr[4][4];
            #pragma unroll
            for (int mi = 0; mi < 4; mi++) {
                uint32_t addr = smem_u32(&As[st][k0 + a_kad][a_mad + mi * 16]);
                ldsm_x4_t(afr[mi][0], afr[mi][1], afr[mi][2], afr[mi][3], addr);
            }
            uint32_t bfr[4][2];
            #pragma unroll
            for (int ni = 0; ni < 4; ni++) {
                uint32_t addr = smem_u32(&Bs[st][k0 + b_kad][warp_n * 32 + ni * 8]);
                ldsm_x2_t(bfr[ni][0], bfr[ni][1], addr);
            }
            #pragma unroll
            for (int mi = 0; mi < 4; mi++)
                #pragma unroll
                for (int ni = 0; ni < 4; ni++)
                    mma_bf16(acc[mi][ni][0], acc[mi][ni][1], acc[mi][ni][2], acc[mi][ni][3],
                             afr[mi][0], afr[mi][1], afr[mi][2], afr[mi][3],
                             bfr[ni][0], bfr[ni][1]);
        }
        __syncthreads();
        if (c + 2 < NCHUNK)
            load_stage(st, (c + 2) * BK);
        cp_commit();
    }

    // --------------------------- fused epilogue ---------------------------
    const int g  = lane >> 2;
    const int tg = lane & 3;
    const int base = n * HW;

    float rn2[4][2]; int rm2[4][2];
    #pragma unroll
    for (int mi = 0; mi < 4; mi++) {
        int r = p0 + warp_m * 64 + mi * 16 + g;
        rn2[mi][0] = g_rnorm[base + r];     rm2[mi][0] = RM[base + r];
        rn2[mi][1] = g_rnorm[base + r + 8]; rm2[mi][1] = RM[base + r + 8];
    }
    float in2[4][2]; int im2[4][2];
    #pragma unroll
    for (int ni = 0; ni < 4; ni++) {
        int c = q0 + warp_n * 32 + ni * 8 + tg * 2;
        in2[ni][0] = g_inorm[base + c];     im2[ni][0] = IM[base + c];
        in2[ni][1] = g_inorm[base + c + 1]; im2[ni][1] = IM[base + c + 1];
    }

    float mind = 1e30f;
    #pragma unroll
    for (int mi = 0; mi < 4; mi++)
        #pragma unroll
        for (int ni = 0; ni < 4; ni++)
            #pragma unroll
            for (int r = 0; r < 4; r++) {
                float d = rn2[mi][r >> 1] + in2[ni][r & 1] - 2.0f * acc[mi][ni][r];
                acc[mi][ni][r] = d;
                mind = fminf(mind, d);
            }
    const bool fast = __all_sync(0xffffffffu, mind > 18.0f);

    float rowS[4][2], rowM[4][2], colS[4][2], colM[4][2];
    #pragma unroll
    for (int i = 0; i < 4; i++)
        #pragma unroll
        for (int j = 0; j < 2; j++) {
            rowS[i][j] = 0.f; rowM[i][j] = 0.f;
            colS[i][j] = 0.f; colM[i][j] = 0.f;
        }

    if (fast) {
        // Exact: dist > 18 => expf(-dist) < 2^-25 => expf(e1/10) == 1.0f in fp32.
        #pragma unroll
        for (int mi = 0; mi < 4; mi++)
            #pragma unroll
            for (int ni = 0; ni < 4; ni++)
                #pragma unroll
                for (int r = 0; r < 4; r++) {
                    int ri = r >> 1, ci = r & 1;
                    if (rm2[mi][ri] == im2[ni][ci]) {
                        rowM[mi][ri] += 1.0f;
                        colM[ni][ci] += 1.0f;
                    }
                }
        #pragma unroll
        for (int i = 0; i < 4; i++) {
            rowS[i][0] = 8.0f; rowS[i][1] = 8.0f;
            colS[i][0] = 8.0f; colS[i][1] = 8.0f;
        }
    } else {
        #pragma unroll
        for (int mi = 0; mi < 4; mi++)
            #pragma unroll
            for (int ni = 0; ni < 4; ni++)
                #pragma unroll
                for (int r = 0; r < 4; r++) {
                    int ri = r >> 1, ci = r & 1;
                    float d = acc[mi][ni][r];
                    float logit = (d > 18.0f) ? 1.0f : __expf(__expf(-d) * 0.1f);
                    rowS[mi][ri] += logit;
                    colS[ni][ci] += logit;
                    if (rm2[mi][ri] == im2[ni][ci]) {
                        rowM[mi][ri] += logit;
                        colM[ni][ci] += logit;
                    }
                }
    }

    // Row reduce across tg: xor 1, 2.
    #pragma unroll
    for (int mi = 0; mi < 4; mi++)
        #pragma unroll
        for (int ri = 0; ri < 2; ri++) {
            float v = rowS[mi][ri], m = rowM[mi][ri];
            v += __shfl_xor_sync(0xffffffffu, v, 1);
            v += __shfl_xor_sync(0xffffffffu, v, 2);
            m += __shfl_xor_sync(0xffffffffu, m, 1);
            m += __shfl_xor_sync(0xffffffffu, m, 2);
            if (tg == 0) {
                int r = p0 + warp_m * 64 + mi * 16 + g + ri * 8;
                atomicAdd(&g_rowL [base + r], v);
                atomicAdd(&g_rowLM[base + r], m);
            }
        }

    // Col reduce across g: xor 4, 8, 16.
    #pragma unroll
    for (int ni = 0; ni < 4; ni++)
        #pragma unroll
        for (int ci = 0; ci < 2; ci++) {
            float v = colS[ni][ci], m = colM[ni][ci];
            v += __shfl_xor_sync(0xffffffffu, v, 4);
            v += __shfl_xor_sync(0xffffffffu, v, 8);
            v += __shfl_xor_sync(0xffffffffu, v, 16);
            m += __shfl_xor_sync(0xffffffffu, m, 4);
            m += __shfl_xor_sync(0xffffffffu, m, 8);
            m += __shfl_xor_sync(0xffffffffu, m, 16);
            if (g == 0) {
                int c = q0 + warp_n * 32 + ni * 8 + tg * 2 + ci;
                atomicAdd(&g_colL [base + c], v);
                atomicAdd(&g_colLM[base + c], m);
            }
        }
}

// ---------------------------------------------------------------------------
// reduce: masked -log sums across 64 blocks -> g_tot/g_cnt; the LAST block
// to finish performs the final division (fused div launch).
// ---------------------------------------------------------------------------
__global__ __launch_bounds__(256)
void reduce_kernel(const int* __restrict__ RM, const int* __restrict__ IM,
                   float* __restrict__ out)
{
    __shared__ float s_t[256];
    __shared__ float s_c[256];
    __shared__ unsigned int s_rank;
    int tid = threadIdx.x;
    int j = blockIdx.x * 128 + (tid & 127);      // 64 blocks x 128 = 8192
    bool isRow = tid < 128;

    float tot = 0.f, cnt = 0.f;
    if (isRow) {
        float l = g_rowL[j] + 1e-6f;
        float v = g_rowLM[j] / l;
        if (RM[j] > 0 && v != 0.0f) { tot = -__logf(v); cnt = 1.f; }
    } else {
        float l = g_colL[j] + 1e-6f;
        float v = g_colLM[j] / l;
        if (IM[j] > 0 && v != 0.0f) { tot = -__logf(v); cnt = 1.f; }
    }
    s_t[tid] = tot; s_c[tid] = cnt;
    __syncthreads();
    for (int s = 128; s > 0; s >>= 1) {
        if (tid < s) { s_t[tid] += s_t[tid + s]; s_c[tid] += s_c[tid + s]; }
        __syncthreads();
    }
    if (tid == 0) {
        atomicAdd(&g_tot, s_t[0]);
        atomicAdd(&g_cnt, s_c[0]);
        __threadfence();
        s_rank = atomicAdd(&g_rctr, 1u);
    }
    __syncthreads();
    if (s_rank == RBLK - 1 && tid == 0) {
        out[0] = g_tot / g_cnt;
    }
}

// ---------------------------------------------------------------------------
extern "C" void kernel_launch(void* const* d_in, const int* in_sizes, int n_in,
                              void* d_out, int out_size)
{
    const float* R  = (const float*)d_in[0];   // rgb_map  (N,C,H,W) fp32
    const float* I  = (const float*)d_in[1];   // ir_map   (N,C,H,W) fp32
    const int*   RM = (const int*)  d_in[2];   // rgb_mask (N,H,W)   int32
    const int*   IM = (const int*)  d_in[3];   // ir_mask  (N,H,W)   int32
    float* out = (float*)d_out;

    prep_kernel<<<512, 256>>>(R, I);

    dim3 grid(HW / BN, HW / BM, NB);           // (8, 8, 8) = 512 CTAs
    tile_kernel<<<grid, 256>>>(RM, IM);

    reduce_kernel<<<RBLK, 256>>>(RM, IM, out);
}